// round 6
// baseline (speedup 1.0000x reference)
#include <cuda_runtime.h>
#include <cuda_fp16.h>
#include <cstdint>

// ---------------- problem constants ----------------
#define M_TOTAL 8192
#define N_TOTAL 4096
#define K_TOTAL 4096

// ---------------- GEMM tiling ----------------
#define BM 128
#define BN 128
#define BK 32                      // halfs of k per sub-chunk (two k16 MMA groups)
#define SUBSTAGES 6                // ring of BK=32 sub-stage buffers
#define ROW_H 32                   // halfs per row per sub-stage (64B, conflict-free)
#define A_STAGE_H (BM * ROW_H)     // 4096 halfs = 8KB
#define B_STAGE_H (BN * ROW_H)
#define SMEM_BYTES (SUBSTAGES * (A_STAGE_H + B_STAGE_H) * 2)   // 98304 -> 2 CTAs/SM

// Scratch: fp16, fragment-permuted (same layout as R5). Within each 32-k block,
// thread t4's 16B at offset t4*8 halfs holds its m16n8k16 fragment pairs for
// both k16 groups: {x=gr0lo, y=gr0hi, z=gr1lo, w=gr1hi}.
__device__ __half g_A[(size_t)M_TOTAL * K_TOTAL];   // 67 MB
__device__ __half g_WB[(size_t)N_TOTAL * K_TOTAL];  // 33.5 MB

// ---------------- fused prep kernel (unchanged from R5) ----------------
#define NW_BLOCKS ((N_TOTAL * K_TOTAL) / 1024)   // 16384
#define NA_BLOCKS ((M_TOTAL * K_TOTAL) / 1024)   // 32768

__global__ __launch_bounds__(256)
void prep_kernel(const float* __restrict__ data,
                 const float* __restrict__ weight,
                 const float* __restrict__ w_mask) {
    __shared__ float f[1024];
    const int tid = threadIdx.x;
    const bool isW = blockIdx.x < NW_BLOCKS;
    const size_t base = isW ? (size_t)blockIdx.x * 1024
                            : (size_t)(blockIdx.x - NW_BLOCKS) * 1024;
    if (isW) {
        float4 v = reinterpret_cast<const float4*>(weight + base)[tid];
        float4 m = reinterpret_cast<const float4*>(w_mask + base)[tid];
        v.x *= m.x; v.y *= m.y; v.z *= m.z; v.w *= m.w;
        reinterpret_cast<float4*>(f)[tid] = v;
    } else {
        reinterpret_cast<float4*>(f)[tid] = reinterpret_cast<const float4*>(data + base)[tid];
    }
    __syncthreads();
    const int bb = tid >> 3;
    const int t  = (tid & 7) >> 1;
    const int gr = tid & 1;
    const int k0 = bb * 32 + gr * 16 + 2 * t;
    __half2 h0 = __floats2half2_rn(f[k0],     f[k0 + 1]);
    __half2 h1 = __floats2half2_rn(f[k0 + 8], f[k0 + 9]);
    __half* outp = isW ? g_WB : g_A;
    uint2 pk;
    pk.x = *reinterpret_cast<uint32_t*>(&h0);
    pk.y = *reinterpret_cast<uint32_t*>(&h1);
    reinterpret_cast<uint2*>(outp + base)[tid] = pk;
}

// ---------------- GEMM ----------------
__device__ __forceinline__ void cp_async16(void* dst, const void* src) {
    unsigned sdst = (unsigned)__cvta_generic_to_shared(dst);
    asm volatile("cp.async.cg.shared.global [%0], [%1], 16;" :: "r"(sdst), "l"(src));
}

__device__ __forceinline__ void mma_f16(float* c,
                                        unsigned a0, unsigned a1, unsigned a2, unsigned a3,
                                        unsigned b0, unsigned b1) {
    asm volatile(
        "mma.sync.aligned.m16n8k16.row.col.f32.f16.f16.f32 "
        "{%0,%1,%2,%3}, {%4,%5,%6,%7}, {%8,%9}, {%0,%1,%2,%3};"
        : "+f"(c[0]), "+f"(c[1]), "+f"(c[2]), "+f"(c[3])
        : "r"(a0), "r"(a1), "r"(a2), "r"(a3), "r"(b0), "r"(b1));
}

__global__ __launch_bounds__(128, 2)
void gemm_f16_kernel(float* __restrict__ out, const float* __restrict__ bias) {
    extern __shared__ __half smem[];
    __half* As = smem;                             // [SUBSTAGES][BM][ROW_H]
    __half* Bs = smem + SUBSTAGES * A_STAGE_H;     // [SUBSTAGES][BN][ROW_H]

    const int tid  = threadIdx.x;
    const int wid  = tid >> 5;
    const int lane = tid & 31;
    const int g    = lane >> 2;        // 0..7
    const int t4   = lane & 3;         // 0..3

    const int warp_m = (wid & 1) * 64;   // 0,64
    const int warp_n = (wid >> 1) * 64;  // 0,64

    const int bm = blockIdx.y * BM;
    const int bn = blockIdx.x * BN;

    const __half* Abase = g_A  + (size_t)bm * K_TOTAL;
    const __half* Bbase = g_WB + (size_t)bn * K_TOTAL;

    float acc[4][8][4];
    #pragma unroll
    for (int i = 0; i < 4; i++)
        #pragma unroll
        for (int j = 0; j < 8; j++)
            #pragma unroll
            for (int r = 0; r < 4; r++) acc[i][j][r] = 0.0f;

    // Load one BK=32 sub-chunk ck into ring buffer ck%6. 4+4 cp.async/thread.
    auto load_chunk = [&](int ck) {
        const int buf = ck % SUBSTAGES;
        const int k0 = ck * BK;
        #pragma unroll
        for (int it = 0; it < 4; it++) {          // A: 512 x 16B
            int idx = tid + it * 128;
            int row = idx >> 2, ch = idx & 3;
            cp_async16(&As[buf * A_STAGE_H + row * ROW_H + ch * 8],
                       Abase + (size_t)row * K_TOTAL + k0 + ch * 8);
        }
        #pragma unroll
        for (int it = 0; it < 4; it++) {          // B: 512 x 16B
            int idx = tid + it * 128;
            int row = idx >> 2, ch = idx & 3;
            cp_async16(&Bs[buf * B_STAGE_H + row * ROW_H + ch * 8],
                       Bbase + (size_t)row * K_TOTAL + k0 + ch * 8);
        }
    };

    // Consume one BK=32 sub-chunk from ring buffer ck%6: 16 LDS.128 + 64 HMMA.
    auto consume_chunk = [&](int ck) {
        const int buf = ck % SUBSTAGES;
        const __half* Ab = &As[buf * A_STAGE_H];
        const __half* Bb = &Bs[buf * B_STAGE_H];
        uint4 aQ[4][2];
        uint4 bQ[8];
        #pragma unroll
        for (int i = 0; i < 4; i++) {
            aQ[i][0] = *reinterpret_cast<const uint4*>(Ab + (warp_m + i * 16 + g)     * ROW_H + t4 * 8);
            aQ[i][1] = *reinterpret_cast<const uint4*>(Ab + (warp_m + i * 16 + g + 8) * ROW_H + t4 * 8);
        }
        #pragma unroll
        for (int j = 0; j < 8; j++)
            bQ[j] = *reinterpret_cast<const uint4*>(Bb + (warp_n + j * 8 + g) * ROW_H + t4 * 8);
        #pragma unroll
        for (int i = 0; i < 4; i++) {
            #pragma unroll
            for (int j = 0; j < 8; j++) {
                mma_f16(acc[i][j], aQ[i][0].x, aQ[i][1].x, aQ[i][0].y, aQ[i][1].y,
                        bQ[j].x, bQ[j].y);
                mma_f16(acc[i][j], aQ[i][0].z, aQ[i][1].z, aQ[i][0].w, aQ[i][1].w,
                        bQ[j].z, bQ[j].w);
            }
        }
    };

    // Prologue: pairs 0 and 1 in flight (sub-chunks 0..3), one group per pair.
    load_chunk(0); load_chunk(1);
    asm volatile("cp.async.commit_group;");
    load_chunk(2); load_chunk(3);
    asm volatile("cp.async.commit_group;");

    const int PAIRS = K_TOTAL / (2 * BK);   // 64
    for (int p = 0; p < PAIRS; ++p) {
        // Ensure pair p complete (leave at most the newest pair pending).
        asm volatile("cp.async.wait_group 1;");
        __syncthreads();
        if (p + 2 < PAIRS) {
            load_chunk(2 * p + 4);
            load_chunk(2 * p + 5);
            asm volatile("cp.async.commit_group;");
        } else {
            asm volatile("cp.async.commit_group;");
        }
        consume_chunk(2 * p);
        consume_chunk(2 * p + 1);
    }

    // Epilogue: c0,c1 @ (g, 2t4/2t4+1); c2,c3 @ row g+8. float2 STG, bias fused.
    const int row0 = bm + warp_m;
    const int col0 = bn + warp_n;
    #pragma unroll
    for (int j = 0; j < 8; j++) {
        int c = col0 + j * 8 + t4 * 2;
        float b0 = __ldg(bias + c), b1 = __ldg(bias + c + 1);
        #pragma unroll
        for (int i = 0; i < 4; i++) {
            int r = row0 + i * 16 + g;
            float2 v0 = make_float2(acc[i][j][0] + b0, acc[i][j][1] + b1);
            float2 v1 = make_float2(acc[i][j][2] + b0, acc[i][j][3] + b1);
            *reinterpret_cast<float2*>(out + (size_t)r * N_TOTAL + c) = v0;
            *reinterpret_cast<float2*>(out + (size_t)(r + 8) * N_TOTAL + c) = v1;
        }
    }
}

extern "C" void kernel_launch(void* const* d_in, const int* in_sizes, int n_in,
                              void* d_out, int out_size) {
    const float* data   = (const float*)d_in[0];
    const float* weight = (const float*)d_in[1];
    const float* w_mask = (const float*)d_in[2];
    const float* bias_p = (const float*)d_in[3];
    float* out = (float*)d_out;

    prep_kernel<<<NW_BLOCKS + NA_BLOCKS, 256>>>(data, weight, w_mask);

    cudaFuncSetAttribute(gemm_f16_kernel,
                         cudaFuncAttributeMaxDynamicSharedMemorySize, SMEM_BYTES);
    dim3 grid(N_TOTAL / BN, M_TOTAL / BM);   // (32, 64)
    gemm_f16_kernel<<<grid, 128, SMEM_BYTES>>>(out, bias_p);
}

// round 7
// speedup vs baseline: 1.0044x; 1.0044x over previous
#include <cuda_runtime.h>
#include <cuda_fp16.h>
#include <cstdint>

// ---------------- problem constants ----------------
#define M_TOTAL 8192
#define N_TOTAL 4096
#define K_TOTAL 4096

// ---------------- GEMM tiling ----------------
#define BM 128
#define BN 128
#define BK 32                      // halfs of k per stage (two k16 MMA groups)
#define STAGES 4                   // power-of-2 ring
#define ROW_H 32                   // halfs per row per stage (64B rows, conflict-free)
#define A_STAGE_H (BM * ROW_H)     // 4096 halfs = 8KB
#define B_STAGE_H (BN * ROW_H)
#define SMEM_BYTES (STAGES * (A_STAGE_H + B_STAGE_H) * 2)   // 65536 -> 2 CTAs/SM

// Scratch: fp16, fragment-permuted (layout as R5): within each 32-k block,
// thread t4's 16B at half-offset t4*8 holds its m16n8k16 fragment pairs for
// both k16 groups: {x=gr0lo, y=gr0hi, z=gr1lo, w=gr1hi}.
__device__ __half g_A[(size_t)M_TOTAL * K_TOTAL];   // 67 MB
__device__ __half g_WB[(size_t)N_TOTAL * K_TOTAL];  // 33.5 MB

// ---------------- fused prep kernel (unchanged from R5) ----------------
#define NW_BLOCKS ((N_TOTAL * K_TOTAL) / 1024)   // 16384
#define NA_BLOCKS ((M_TOTAL * K_TOTAL) / 1024)   // 32768

__global__ __launch_bounds__(256)
void prep_kernel(const float* __restrict__ data,
                 const float* __restrict__ weight,
                 const float* __restrict__ w_mask) {
    __shared__ float f[1024];
    const int tid = threadIdx.x;
    const bool isW = blockIdx.x < NW_BLOCKS;
    const size_t base = isW ? (size_t)blockIdx.x * 1024
                            : (size_t)(blockIdx.x - NW_BLOCKS) * 1024;
    if (isW) {
        float4 v = reinterpret_cast<const float4*>(weight + base)[tid];
        float4 m = reinterpret_cast<const float4*>(w_mask + base)[tid];
        v.x *= m.x; v.y *= m.y; v.z *= m.z; v.w *= m.w;
        reinterpret_cast<float4*>(f)[tid] = v;
    } else {
        reinterpret_cast<float4*>(f)[tid] = reinterpret_cast<const float4*>(data + base)[tid];
    }
    __syncthreads();
    const int bb = tid >> 3;
    const int t  = (tid & 7) >> 1;
    const int gr = tid & 1;
    const int k0 = bb * 32 + gr * 16 + 2 * t;
    __half2 h0 = __floats2half2_rn(f[k0],     f[k0 + 1]);
    __half2 h1 = __floats2half2_rn(f[k0 + 8], f[k0 + 9]);
    __half* outp = isW ? g_WB : g_A;
    uint2 pk;
    pk.x = *reinterpret_cast<uint32_t*>(&h0);
    pk.y = *reinterpret_cast<uint32_t*>(&h1);
    reinterpret_cast<uint2*>(outp + base)[tid] = pk;
}

// ---------------- GEMM ----------------
__device__ __forceinline__ void cp_async16(void* dst, const void* src) {
    unsigned sdst = (unsigned)__cvta_generic_to_shared(dst);
    asm volatile("cp.async.cg.shared.global [%0], [%1], 16;" :: "r"(sdst), "l"(src));
}

__device__ __forceinline__ void mma_f16(float* c,
                                        unsigned a0, unsigned a1, unsigned a2, unsigned a3,
                                        unsigned b0, unsigned b1) {
    asm volatile(
        "mma.sync.aligned.m16n8k16.row.col.f32.f16.f16.f32 "
        "{%0,%1,%2,%3}, {%4,%5,%6,%7}, {%8,%9}, {%0,%1,%2,%3};"
        : "+f"(c[0]), "+f"(c[1]), "+f"(c[2]), "+f"(c[3])
        : "r"(a0), "r"(a1), "r"(a2), "r"(a3), "r"(b0), "r"(b1));
}

__global__ __launch_bounds__(256, 2)
void gemm_f16_kernel(float* __restrict__ out, const float* __restrict__ bias) {
    extern __shared__ __half smem[];
    __half* As = smem;                           // [STAGES][BM][ROW_H]
    __half* Bs = smem + STAGES * A_STAGE_H;      // [STAGES][BN][ROW_H]

    const int tid  = threadIdx.x;
    const int wid  = tid >> 5;
    const int lane = tid & 31;
    const int g    = lane >> 2;        // 0..7
    const int t4   = lane & 3;         // 0..3

    const int warp_m = (wid & 1) * 64;      // 0,64
    const int warp_n = (wid >> 1) * 32;     // 0,32,64,96

    const int bm = blockIdx.y * BM;
    const int bn = blockIdx.x * BN;

    const __half* Abase = g_A  + (size_t)bm * K_TOTAL;
    const __half* Bbase = g_WB + (size_t)bn * K_TOTAL;

    float acc[4][4][4];
    #pragma unroll
    for (int i = 0; i < 4; i++)
        #pragma unroll
        for (int j = 0; j < 4; j++)
            #pragma unroll
            for (int r = 0; r < 4; r++) acc[i][j][r] = 0.0f;

    // Per-warp fragment smem offsets (halfs), hoisted.
    const int aoff0 = (warp_m + g) * ROW_H + t4 * 8;       // + i*16*ROW_H, +8*ROW_H
    const int boff0 = (warp_n + g) * ROW_H + t4 * 8;       // + j*8*ROW_H

    // Stage loader: A 512 + B 512 x 16B chunks over 256 threads -> 2+2 each.
    auto load_stage = [&](int kt) {
        const int buf = kt & (STAGES - 1);
        const int k0 = kt * BK;
        #pragma unroll
        for (int it = 0; it < 2; it++) {          // A
            int idx = tid + it * 256;
            int row = idx >> 2, ch = idx & 3;
            cp_async16(&As[buf * A_STAGE_H + row * ROW_H + ch * 8],
                       Abase + (size_t)row * K_TOTAL + k0 + ch * 8);
        }
        #pragma unroll
        for (int it = 0; it < 2; it++) {          // B
            int idx = tid + it * 256;
            int row = idx >> 2, ch = idx & 3;
            cp_async16(&Bs[buf * B_STAGE_H + row * ROW_H + ch * 8],
                       Bbase + (size_t)row * K_TOTAL + k0 + ch * 8);
        }
        asm volatile("cp.async.commit_group;");
    };

    // Prologue: 3 stages in flight.
    load_stage(0);
    load_stage(1);
    load_stage(2);

    const int KT = K_TOTAL / BK;  // 128
    for (int kt = 0; kt < KT; ++kt) {
        // Stage kt complete when at most 2 newer groups pending.
        asm volatile("cp.async.wait_group 2;");
        __syncthreads();
        if (kt + 3 < KT) {
            load_stage(kt + 3);
        } else {
            asm volatile("cp.async.commit_group;");
        }

        const int buf = kt & (STAGES - 1);
        const __half* Ab = &As[buf * A_STAGE_H];
        const __half* Bb = &Bs[buf * B_STAGE_H];

        // B fragments for this warp's 32 columns: 4 x LDS.128
        uint4 bQ[4];
        #pragma unroll
        for (int j = 0; j < 4; j++)
            bQ[j] = *reinterpret_cast<const uint4*>(Bb + boff0 + j * 8 * ROW_H);

        // A fragments loaded per m-tile to bound live registers.
        #pragma unroll
        for (int i = 0; i < 4; i++) {
            uint4 a0 = *reinterpret_cast<const uint4*>(Ab + aoff0 + i * 16 * ROW_H);
            uint4 a1 = *reinterpret_cast<const uint4*>(Ab + aoff0 + i * 16 * ROW_H + 8 * ROW_H);
            #pragma unroll
            for (int j = 0; j < 4; j++) {
                mma_f16(acc[i][j], a0.x, a1.x, a0.y, a1.y, bQ[j].x, bQ[j].y);
                mma_f16(acc[i][j], a0.z, a1.z, a0.w, a1.w, bQ[j].z, bQ[j].w);
            }
        }
    }

    // Epilogue: c0,c1 @ (g, 2t4/2t4+1); c2,c3 @ row g+8. float2 STG, bias fused.
    const int row0 = bm + warp_m;
    const int col0 = bn + warp_n;
    #pragma unroll
    for (int j = 0; j < 4; j++) {
        int c = col0 + j * 8 + t4 * 2;
        float b0 = __ldg(bias + c), b1 = __ldg(bias + c + 1);
        #pragma unroll
        for (int i = 0; i < 4; i++) {
            int r = row0 + i * 16 + g;
            float2 v0 = make_float2(acc[i][j][0] + b0, acc[i][j][1] + b1);
            float2 v1 = make_float2(acc[i][j][2] + b0, acc[i][j][3] + b1);
            *reinterpret_cast<float2*>(out + (size_t)r * N_TOTAL + c) = v0;
            *reinterpret_cast<float2*>(out + (size_t)(r + 8) * N_TOTAL + c) = v1;
        }
    }
}

extern "C" void kernel_launch(void* const* d_in, const int* in_sizes, int n_in,
                              void* d_out, int out_size) {
    const float* data   = (const float*)d_in[0];
    const float* weight = (const float*)d_in[1];
    const float* w_mask = (const float*)d_in[2];
    const float* bias_p = (const float*)d_in[3];
    float* out = (float*)d_out;

    prep_kernel<<<NW_BLOCKS + NA_BLOCKS, 256>>>(data, weight, w_mask);

    cudaFuncSetAttribute(gemm_f16_kernel,
                         cudaFuncAttributeMaxDynamicSharedMemorySize, SMEM_BYTES);
    dim3 grid(N_TOTAL / BN, M_TOTAL / BM);   // (32, 64)
    gemm_f16_kernel<<<grid, 256, SMEM_BYTES>>>(out, bias_p);
}